// round 1
// baseline (speedup 1.0000x reference)
#include <cuda_runtime.h>
#include <cstdint>

// BinaryConv2d: x (8,16,1024,1024) f32, weight (16,16,3,3) in {0,1} -> {+1,-1}
// conv stride (2,2), pad (1,1) -> out (8,16,512,512)
//
// Strategy: multiply-free conv expressed as FFMA2 (fma.rn.f32x2) with +/-1
// sign operands packed over output-channel pairs. Each thread computes
// 4 consecutive output x positions for ALL 16 output channels.
// Input tiles double-buffered in shared via cp.async (zero-fill handles pad).

#define N_BATCH 8
#define C_IN    16
#define C_OUT   16
#define IN_HW   1024
#define OUT_HW  512

#define TH 16              // output rows per block
#define TW 32              // output cols per block
#define PX 4               // output cols per thread
#define NTHREADS 128       // (TW/PX) * TH = 8 * 16

#define TILE_H 33          // 2*TH + 1
#define TILE_W 65          // 2*TW + 1
#define TILE_ELEMS (TILE_H * TILE_W)   // 2145

__device__ __forceinline__ unsigned long long bcast2(float x) {
    unsigned long long r;
    asm("mov.b64 %0, {%1, %1};" : "=l"(r) : "f"(x));
    return r;
}

__device__ __forceinline__ void ffma2(unsigned long long& acc,
                                      unsigned long long a,
                                      unsigned long long b) {
    asm("fma.rn.f32x2 %0, %1, %2, %0;" : "+l"(acc) : "l"(a), "l"(b));
}

__device__ __forceinline__ float2 unpack2(unsigned long long v) {
    float2 f;
    asm("mov.b64 {%0, %1}, %2;" : "=f"(f.x), "=f"(f.y) : "l"(v));
    return f;
}

__device__ __forceinline__ void cp_async_zfill(uint32_t saddr, const float* gptr, int sz) {
    asm volatile("cp.async.ca.shared.global [%0], [%1], 4, %2;\n"
                 :: "r"(saddr), "l"(gptr), "r"(sz));
}

__global__ void __launch_bounds__(NTHREADS, 4)
binconv_kernel(const float* __restrict__ x,
               const float* __restrict__ w,
               float* __restrict__ out) {
    __shared__ float s_sgn[C_IN * 9 * C_OUT];                 // [c][tap][oc], oc fastest
    __shared__ __align__(16) float s_in[2][TILE_ELEMS];

    const int tid = threadIdx.x;
    const int tx  = tid & 7;      // 0..7  (x group of 4 px)
    const int ty  = tid >> 3;     // 0..15 (output row)

    const int n  = blockIdx.z;
    const int y0 = blockIdx.y * TH;
    const int x0 = blockIdx.x * TW;

    // ---- decode weights into shared sign table (packed-pair friendly) ----
    #pragma unroll
    for (int idx = tid; idx < C_OUT * C_IN * 9; idx += NTHREADS) {
        int oc  = idx / (C_IN * 9);
        int rem = idx - oc * (C_IN * 9);    // c*9 + tap
        float wv = w[idx];                  // layout: oc major, then c, then tap
        s_sgn[rem * C_OUT + oc] = (wv == 1.0f) ? 1.0f : -1.0f;
    }

    // ---- input tile coordinates (padded conv: input row = 2y-1+r) ----
    const int gy0 = 2 * y0 - 1;
    const int gx0 = 2 * x0 - 1;
    const float* xn = x + (size_t)n * C_IN * IN_HW * IN_HW;

    // prefetch helper (inlined via lambda-style macro)
    auto prefetch = [&](int c, int buf) {
        const float* xc = xn + (size_t)c * IN_HW * IN_HW;
        uint32_t sbase = (uint32_t)__cvta_generic_to_shared(&s_in[buf][0]);
        #pragma unroll
        for (int it = 0; it < (TILE_ELEMS + NTHREADS - 1) / NTHREADS; ++it) {
            int idx = tid + it * NTHREADS;
            if (idx < TILE_ELEMS) {
                int row = idx / TILE_W;
                int col = idx - row * TILE_W;
                int gy = gy0 + row;
                int gx = gx0 + col;
                bool ok = ((unsigned)gy < (unsigned)IN_HW) && ((unsigned)gx < (unsigned)IN_HW);
                const float* src = ok ? (xc + (size_t)gy * IN_HW + gx) : xc;
                cp_async_zfill(sbase + 4u * idx, src, ok ? 4 : 0);
            }
        }
        asm volatile("cp.async.commit_group;\n");
    };

    // accumulators: [oc_pair 0..7][px 0..3] packed f32x2
    unsigned long long acc[8][4];
    #pragma unroll
    for (int i = 0; i < 8; ++i)
        #pragma unroll
        for (int p = 0; p < 4; ++p)
            acc[i][p] = 0ull;

    prefetch(0, 0);

    for (int c = 0; c < C_IN; ++c) {
        if (c + 1 < C_IN) {
            prefetch(c + 1, (c + 1) & 1);
            asm volatile("cp.async.wait_group 1;\n");
        } else {
            asm volatile("cp.async.wait_group 0;\n");
        }
        __syncthreads();   // tile for channel c visible (also covers sign decode on c==0)

        const float* bp = &s_in[c & 1][0];
        const float* sgn_c = s_sgn + c * 9 * C_OUT;

        #pragma unroll
        for (int r = 0; r < 3; ++r) {
            const float* rowp = bp + (2 * ty + r) * TILE_W + 8 * tx;
            unsigned long long xp[10];
            #pragma unroll
            for (int k = 0; k < 10; ++k)
                xp[k] = bcast2(rowp[k]);

            #pragma unroll
            for (int j = 0; j < 3; ++j) {
                const unsigned long long* sp =
                    (const unsigned long long*)(sgn_c + (r * 3 + j) * C_OUT);
                unsigned long long sv[8];
                #pragma unroll
                for (int i = 0; i < 8; ++i)
                    sv[i] = sp[i];          // broadcast LDS.64

                #pragma unroll
                for (int p = 0; p < 4; ++p) {
                    unsigned long long xv = xp[2 * p + j];
                    #pragma unroll
                    for (int i = 0; i < 8; ++i)
                        ffma2(acc[i][p], xv, sv[i]);
                }
            }
        }
        __syncthreads();   // done with this buffer before it's refilled
    }

    // ---- writeout: 16 oc x 4 consecutive x -> float4 per oc ----
    const int oy = y0 + ty;
    const int ox = x0 + 4 * tx;
    float* ob = out + (((size_t)n * C_OUT) * OUT_HW + oy) * OUT_HW + ox;

    #pragma unroll
    for (int i = 0; i < 8; ++i) {
        float2 f0 = unpack2(acc[i][0]);
        float2 f1 = unpack2(acc[i][1]);
        float2 f2 = unpack2(acc[i][2]);
        float2 f3 = unpack2(acc[i][3]);
        float4 lo = make_float4(f0.x, f1.x, f2.x, f3.x);
        float4 hi = make_float4(f0.y, f1.y, f2.y, f3.y);
        *(float4*)(ob + (size_t)(2 * i)     * OUT_HW * OUT_HW) = lo;
        *(float4*)(ob + (size_t)(2 * i + 1) * OUT_HW * OUT_HW) = hi;
    }
}

extern "C" void kernel_launch(void* const* d_in, const int* in_sizes, int n_in,
                              void* d_out, int out_size) {
    const float* x = (const float*)d_in[0];
    const float* w = (const float*)d_in[1];
    float* out = (float*)d_out;

    dim3 grid(OUT_HW / TW, OUT_HW / TH, N_BATCH);   // (16, 32, 8)
    dim3 block(NTHREADS);
    binconv_kernel<<<grid, block>>>(x, w, out);
}